// round 13
// baseline (speedup 1.0000x reference)
#include <cuda_runtime.h>
#include <cuda_fp16.h>
#include <cstdint>

#define BATCH 4
#define TLEN  4096
#define HDIM  1024
#define MROWS (BATCH * TLEN)   // 16384
#define WIN   8
#define WSZ   9

// Scratch (device globals; cudaMalloc forbidden)
__device__ __half g_qh[MROWS * HDIM];
__device__ __half g_kh[MROWS * HDIM];
__device__ __half g_vh[MROWS * HDIM];
__device__ __half g_xh[MROWS * HDIM];        // fp16 states
__device__ __half g_wh[3 * HDIM * HDIM];     // fp16 Wq|Wk|Wv

// ---------------- PTX helpers ----------------
__device__ __forceinline__ uint32_t smem_u32(const void* p) {
    uint32_t a;
    asm("{ .reg .u64 t; cvta.to.shared.u64 t, %1; cvt.u32.u64 %0, t; }" : "=r"(a) : "l"(p));
    return a;
}
__device__ __forceinline__ void cp_async16(uint32_t sdst, const void* g) {
    asm volatile("cp.async.cg.shared.global [%0], [%1], 16;" :: "r"(sdst), "l"(g));
}
__device__ __forceinline__ void cp_commit() {
    asm volatile("cp.async.commit_group;" ::: "memory");
}
template<int N>
__device__ __forceinline__ void cp_wait() {
    asm volatile("cp.async.wait_group %0;" :: "n"(N) : "memory");
}
__device__ __forceinline__ void ldmatrix_x4(uint32_t r[4], uint32_t addr) {
    asm volatile("ldmatrix.sync.aligned.m8n8.x4.shared.b16 {%0,%1,%2,%3}, [%4];"
                 : "=r"(r[0]), "=r"(r[1]), "=r"(r[2]), "=r"(r[3]) : "r"(addr));
}
__device__ __forceinline__ void mma_f16(float c[4], const uint32_t a[4], const uint32_t b[2]) {
    asm volatile(
        "mma.sync.aligned.m16n8k16.row.col.f32.f16.f16.f32 "
        "{%0,%1,%2,%3}, {%4,%5,%6,%7}, {%8,%9}, {%0,%1,%2,%3};"
        : "+f"(c[0]), "+f"(c[1]), "+f"(c[2]), "+f"(c[3])
        : "r"(a[0]), "r"(a[1]), "r"(a[2]), "r"(a[3]), "r"(b[0]), "r"(b[1]));
}

// ---------------- fused prepass: fp32 -> fp16 (32B per thread) ----------------
__global__ __launch_bounds__(256) void conv_kernel(const float* __restrict__ x,
                                                   const float* __restrict__ Wq,
                                                   const float* __restrict__ Wk,
                                                   const float* __restrict__ Wv) {
    int i = blockIdx.x * 256 + threadIdx.x;        // pair index
    int p = 2 * i;                                 // float4 index
    const float* s; __half* d; int j;
    if (p < 4194304)      { s = x;  d = g_xh;           j = p; }
    else {
        int m = p - 4194304;
        if (m < 262144)      { s = Wq; d = g_wh;           j = m; }
        else if (m < 524288) { s = Wk; d = g_wh + 1048576; j = m - 262144; }
        else                 { s = Wv; d = g_wh + 2097152; j = m - 524288; }
    }
    float4 v0 = ((const float4*)s)[j];
    float4 v1 = ((const float4*)s)[j + 1];
    ((__half2*)d)[2 * j]     = __floats2half2_rn(v0.x, v0.y);
    ((__half2*)d)[2 * j + 1] = __floats2half2_rn(v0.z, v0.w);
    ((__half2*)d)[2 * j + 2] = __floats2half2_rn(v1.x, v1.y);
    ((__half2*)d)[2 * j + 3] = __floats2half2_rn(v1.z, v1.w);
}

// ---------------- fp16 QKV GEMM (frozen from 301.5us build) ----------------
#define BK 64
#define ROW_BYTES 128                  // BK * 2
#define TILE_BYTES (128 * ROW_BYTES)   // 16 KB
#define STAGE_BYTES (2 * TILE_BYTES)   // A + B = 32 KB
#define NSTAGE 3
#define G_SMEM (NSTAGE * STAGE_BYTES)  // 96 KB
#define NK (HDIM / BK)                 // 16

__device__ __forceinline__ uint32_t sw_off(int r, int c) {   // bytes within one tile
    uint32_t off = (uint32_t)(r * ROW_BYTES + (c << 4));
    return off ^ ((off >> 3) & 0x70);
}

__global__ __launch_bounds__(256, 2)
void qkv_gemm_kernel(const float* __restrict__ bq,
                     const float* __restrict__ bk,
                     const float* __restrict__ bv)
{
    extern __shared__ __align__(1024) char smem[];
    const uint32_t sb = smem_u32(smem);

    const int tid  = threadIdx.x;
    const int warp = tid >> 5;
    const int lane = tid & 31;
    const int m0 = blockIdx.x * 128;
    const int n0 = blockIdx.y * 128;
    const int z  = blockIdx.z;

    const __half* Xh = g_xh;
    const __half* Wh = g_wh + (size_t)z * HDIM * HDIM;
    const float* bias = (z == 0) ? bq : (z == 1) ? bk : bv;
    __half* outp = (z == 0) ? g_qh : (z == 1) ? g_kh : g_vh;

    const int wm = (warp & 3) * 32;
    const int wn = (warp >> 2) * 64;

    float c[2][8][4];
    #pragma unroll
    for (int mt = 0; mt < 2; ++mt)
        #pragma unroll
        for (int nt = 0; nt < 8; ++nt)
            #pragma unroll
            for (int i = 0; i < 4; ++i) c[mt][nt][i] = 0.f;

    const int r0g = tid >> 3;          // 0..31 (+32 per pass)
    const int cg  = tid & 7;           // 16B chunk 0..7

    auto load_tile = [&](int kt, int buf) {
        const uint32_t sa  = sb + buf * STAGE_BYTES;
        const uint32_t sbm = sa + TILE_BYTES;
        const int k0 = kt * BK;
        #pragma unroll
        for (int i = 0; i < 4; ++i) {
            int r = r0g + i * 32;
            cp_async16(sa + sw_off(r, cg),
                       Xh + (size_t)(m0 + r) * HDIM + k0 + cg * 8);
            cp_async16(sbm + sw_off(r, cg),
                       Wh + (size_t)(n0 + r) * HDIM + k0 + cg * 8);
        }
        cp_commit();
    };

    load_tile(0, 0);
    load_tile(1, 1);

    const int a_row = wm + (lane & 15);                        // + mt*16
    const int a_ch0 = lane >> 4;                               // + kk/8
    const int b_row = wn + (lane & 7) + ((lane >> 4) << 3);    // + np*16
    const int b_ch0 = (lane >> 3) & 1;                         // + kk/8

    int buf = 0;
    for (int kt = 0; kt < NK; ++kt) {
        cp_wait<1>();
        __syncthreads();
        // buffer (kt+2)%3 == (kt-1)%3: all readers passed the barrier above
        if (kt + 2 < NK) {
            int nb = buf + 2; if (nb >= NSTAGE) nb -= NSTAGE;
            load_tile(kt + 2, nb);
        } else {
            cp_commit();               // keep group arithmetic exact
        }

        const uint32_t sa  = sb + buf * STAGE_BYTES;
        const uint32_t sbm = sa + TILE_BYTES;

        #pragma unroll
        for (int h = 0; h < 4; ++h) {          // kk = 16*h
            uint32_t a[2][4], b[4][4];
            #pragma unroll
            for (int mt = 0; mt < 2; ++mt)
                ldmatrix_x4(a[mt], sa + sw_off(a_row + mt * 16, 2 * h + a_ch0));
            #pragma unroll
            for (int np = 0; np < 4; ++np)
                ldmatrix_x4(b[np], sbm + sw_off(b_row + np * 16, 2 * h + b_ch0));
            #pragma unroll
            for (int mt = 0; mt < 2; ++mt)
                #pragma unroll
                for (int nt = 0; nt < 8; ++nt)
                    mma_f16(c[mt][nt], a[mt], &b[nt >> 1][(nt & 1) * 2]);
        }
        if (++buf == NSTAGE) buf = 0;
    }

    // Epilogue: add bias, fp16 stores
    const int g  = lane >> 2;
    const int tg = lane & 3;
    #pragma unroll
    for (int mt = 0; mt < 2; ++mt) {
        #pragma unroll
        for (int nt = 0; nt < 8; ++nt) {
            int row = m0 + wm + mt * 16 + g;
            int col = n0 + wn + nt * 8 + 2 * tg;
            float b0 = bias[col], b1 = bias[col + 1];
            *(__half2*)(outp + (size_t)row * HDIM + col) =
                __floats2half2_rn(c[mt][nt][0] + b0, c[mt][nt][1] + b1);
            *(__half2*)(outp + (size_t)(row + 8) * HDIM + col) =
                __floats2half2_rn(c[mt][nt][2] + b0, c[mt][nt][3] + b1);
        }
    }
}

// ---------------- sliding-window attention: phased K/V smem reuse, 48 warps/SM ----------------
#define A_ROWS 16
#define A_LOAD 24                      // A_ROWS + WIN halo
#define A_KBYTES (A_LOAD * 2048)       // 48 KB — ONE buffer, reused for K then V
#define A_THREADS 512

__device__ __forceinline__ void dot8(float& acc, uint4 a, uint4 b) {
    const __half2* ah = (const __half2*)&a;
    const __half2* bh = (const __half2*)&b;
    #pragma unroll
    for (int j = 0; j < 4; ++j) {
        float2 af = __half22float2(ah[j]);
        float2 bf = __half22float2(bh[j]);
        acc += af.x * bf.x + af.y * bf.y;
    }
}
__device__ __forceinline__ void axpy8(float o[8], float w, uint4 v) {
    const __half2* vh = (const __half2*)&v;
    #pragma unroll
    for (int j = 0; j < 4; ++j) {
        float2 f = __half22float2(vh[j]);
        o[2 * j]     += w * f.x;
        o[2 * j + 1] += w * f.y;
    }
}

__global__ __launch_bounds__(A_THREADS, 3) void attn_kernel(float* __restrict__ out)
{
    extern __shared__ __align__(16) char asmem[];
    const __half* ts = (const __half*)asmem;    // K in phase 1, V in phase 2
    const uint32_t sb = smem_u32(asmem);

    const int tid = threadIdx.x;
    const int r0  = blockIdx.x * A_ROWS;

    // ---- Phase 1: stage K rows [r0-8, r0+16) ----
    #pragma unroll
    for (int p = 0; p < 6; ++p) {
        int gidx = tid + p * A_THREADS;        // 0..3071
        int s = gidx >> 7, cidx = gidx & 127;
        int gr = r0 - WIN + s; if (gr < 0) gr = 0;
        cp_async16(sb + s * 2048 + cidx * 16,
                   g_kh + (size_t)gr * HDIM + cidx * 8);
    }
    cp_commit();
    cp_wait<0>();
    __syncthreads();

    const int warp = tid >> 5;
    const int lane = tid & 31;

    const int lr  = warp;                  // 0..15
    const int row = r0 + lr;
    const int t   = row & (TLEN - 1);
    const int wstart = (t < WIN) ? (WIN - t) : 0;

    const uint4* q4 = (const uint4*)(g_qh + (size_t)row * HDIM);

    float acc[WSZ];
    #pragma unroll
    for (int w = 0; w < WSZ; ++w) acc[w] = 0.f;

    if (wstart == 0) {
        #pragma unroll
        for (int i = 0; i < 4; ++i) {
            const int idx = lane + i * 32;
            const uint4 qv = q4[idx];
            #pragma unroll
            for (int w = 0; w < WSZ; ++w) {
                const uint4 kv = *(const uint4*)(ts + (size_t)(lr + w) * HDIM + idx * 8);
                dot8(acc[w], qv, kv);
            }
        }
    } else {
        #pragma unroll
        for (int i = 0; i < 4; ++i) {
            const int idx = lane + i * 32;
            const uint4 qv = q4[idx];
            #pragma unroll
            for (int w = 0; w < WSZ; ++w) {
                if (w >= wstart) {
                    const uint4 kv = *(const uint4*)(ts + (size_t)(lr + w) * HDIM + idx * 8);
                    dot8(acc[w], qv, kv);
                }
            }
        }
    }

    float wgt[WSZ];
    float mx = -1e30f;
    #pragma unroll
    for (int w = 0; w < WSZ; ++w) {
        float v = acc[w];
        #pragma unroll
        for (int off = 16; off; off >>= 1)
            v += __shfl_xor_sync(0xFFFFFFFFu, v, off);
        float s = (w >= wstart) ? v * 0.03125f : -1e30f;   // 1/sqrt(1024)
        wgt[w] = s;
        mx = fmaxf(mx, s);
    }
    float den = 0.f;
    #pragma unroll
    for (int w = 0; w < WSZ; ++w) {
        float e = (w >= wstart) ? __expf(wgt[w] - mx) : 0.f;
        wgt[w] = e;
        den += e;
    }
    const float inv = 1.f / den;
    #pragma unroll
    for (int w = 0; w < WSZ; ++w) wgt[w] *= inv;

    // ---- Phase 2: all warps done with K; reload the SAME buffer with V ----
    __syncthreads();
    #pragma unroll
    for (int p = 0; p < 6; ++p) {
        int gidx = tid + p * A_THREADS;
        int s = gidx >> 7, cidx = gidx & 127;
        int gr = r0 - WIN + s; if (gr < 0) gr = 0;
        cp_async16(sb + s * 2048 + cidx * 16,
                   g_vh + (size_t)gr * HDIM + cidx * 8);
    }
    cp_commit();
    cp_wait<0>();
    __syncthreads();

    #pragma unroll
    for (int i = 0; i < 4; ++i) {
        const int idx = lane + i * 32;
        float o[8];
        #pragma unroll
        for (int x = 0; x < 8; ++x) o[x] = 0.f;
        if (wstart == 0) {
            #pragma unroll
            for (int w = 0; w < WSZ; ++w) {
                const uint4 vv = *(const uint4*)(ts + (size_t)(lr + w) * HDIM + idx * 8);
                axpy8(o, wgt[w], vv);
            }
        } else {
            #pragma unroll
            for (int w = 0; w < WSZ; ++w) {
                if (w >= wstart) {
                    const uint4 vv = *(const uint4*)(ts + (size_t)(lr + w) * HDIM + idx * 8);
                    axpy8(o, wgt[w], vv);
                }
            }
        }
        float4* op = (float4*)(out + (size_t)row * HDIM + idx * 8);
        op[0] = make_float4(o[0], o[1], o[2], o[3]);
        op[1] = make_float4(o[4], o[5], o[6], o[7]);
    }
}

// ---------------- launch ----------------
extern "C" void kernel_launch(void* const* d_in, const int* in_sizes, int n_in,
                              void* d_out, int out_size)
{
    const float* states = (const float*)d_in[0];
    const float* Wq = (const float*)d_in[1];
    const float* bq = (const float*)d_in[2];
    const float* Wk = (const float*)d_in[3];
    const float* bk = (const float*)d_in[4];
    const float* Wv = (const float*)d_in[5];
    const float* bv = (const float*)d_in[6];
    float* out = (float*)d_out;

    cudaFuncSetAttribute(qkv_gemm_kernel,
                         cudaFuncAttributeMaxDynamicSharedMemorySize, G_SMEM);
    cudaFuncSetAttribute(attn_kernel,
                         cudaFuncAttributeMaxDynamicSharedMemorySize, A_KBYTES);

    conv_kernel<<<9728, 256>>>(states, Wq, Wk, Wv);

    dim3 grid(MROWS / 128, HDIM / 128, 3);   // 128 x 8 x 3
    qkv_gemm_kernel<<<grid, 256, G_SMEM>>>(bq, bk, bv);

    attn_kernel<<<MROWS / A_ROWS, A_THREADS, A_KBYTES>>>(out);
}

// round 15
// speedup vs baseline: 1.0512x; 1.0512x over previous
#include <cuda_runtime.h>
#include <cuda_fp16.h>
#include <cstdint>

#define BATCH 4
#define TLEN  4096
#define HDIM  1024
#define MROWS (BATCH * TLEN)   // 16384
#define WIN   8
#define WSZ   9

// Scratch (device globals; cudaMalloc forbidden)
__device__ __half g_qh[MROWS * HDIM];
__device__ __half g_kh[MROWS * HDIM];
__device__ __half g_vh[MROWS * HDIM];
__device__ __half g_xh[MROWS * HDIM];        // fp16 states
__device__ __half g_wh[3 * HDIM * HDIM];     // fp16 Wq|Wk|Wv

// ---------------- PTX helpers ----------------
__device__ __forceinline__ uint32_t smem_u32(const void* p) {
    uint32_t a;
    asm("{ .reg .u64 t; cvta.to.shared.u64 t, %1; cvt.u32.u64 %0, t; }" : "=r"(a) : "l"(p));
    return a;
}
__device__ __forceinline__ void cp_async16(uint32_t sdst, const void* g) {
    asm volatile("cp.async.cg.shared.global [%0], [%1], 16;" :: "r"(sdst), "l"(g));
}
__device__ __forceinline__ void cp_commit() {
    asm volatile("cp.async.commit_group;" ::: "memory");
}
template<int N>
__device__ __forceinline__ void cp_wait() {
    asm volatile("cp.async.wait_group %0;" :: "n"(N) : "memory");
}
__device__ __forceinline__ void ldmatrix_x4(uint32_t r[4], uint32_t addr) {
    asm volatile("ldmatrix.sync.aligned.m8n8.x4.shared.b16 {%0,%1,%2,%3}, [%4];"
                 : "=r"(r[0]), "=r"(r[1]), "=r"(r[2]), "=r"(r[3]) : "r"(addr));
}
__device__ __forceinline__ void mma_f16(float c[4], const uint32_t a[4], const uint32_t b[2]) {
    asm volatile(
        "mma.sync.aligned.m16n8k16.row.col.f32.f16.f16.f32 "
        "{%0,%1,%2,%3}, {%4,%5,%6,%7}, {%8,%9}, {%0,%1,%2,%3};"
        : "+f"(c[0]), "+f"(c[1]), "+f"(c[2]), "+f"(c[3])
        : "r"(a[0]), "r"(a[1]), "r"(a[2]), "r"(a[3]), "r"(b[0]), "r"(b[1]));
}

// ---------------- fused prepass: fp32 -> fp16 (32B per thread) ----------------
__global__ __launch_bounds__(256) void conv_kernel(const float* __restrict__ x,
                                                   const float* __restrict__ Wq,
                                                   const float* __restrict__ Wk,
                                                   const float* __restrict__ Wv) {
    int i = blockIdx.x * 256 + threadIdx.x;        // pair index
    int p = 2 * i;                                 // float4 index
    const float* s; __half* d; int j;
    if (p < 4194304)      { s = x;  d = g_xh;           j = p; }
    else {
        int m = p - 4194304;
        if (m < 262144)      { s = Wq; d = g_wh;           j = m; }
        else if (m < 524288) { s = Wk; d = g_wh + 1048576; j = m - 262144; }
        else                 { s = Wv; d = g_wh + 2097152; j = m - 524288; }
    }
    float4 v0 = ((const float4*)s)[j];
    float4 v1 = ((const float4*)s)[j + 1];
    ((__half2*)d)[2 * j]     = __floats2half2_rn(v0.x, v0.y);
    ((__half2*)d)[2 * j + 1] = __floats2half2_rn(v0.z, v0.w);
    ((__half2*)d)[2 * j + 2] = __floats2half2_rn(v1.x, v1.y);
    ((__half2*)d)[2 * j + 3] = __floats2half2_rn(v1.z, v1.w);
}

// ---------------- fp16 QKV GEMM (mainloop frozen; coalesced smem-staged epilogue) ----------------
#define BK 64
#define ROW_BYTES 128                  // BK * 2
#define TILE_BYTES (128 * ROW_BYTES)   // 16 KB
#define STAGE_BYTES (2 * TILE_BYTES)   // A + B = 32 KB
#define NSTAGE 3
#define G_SMEM (NSTAGE * STAGE_BYTES)  // 96 KB
#define NK (HDIM / BK)                 // 16
#define EPAD 136                       // halfs per staged row (128 + 8 pad)

__device__ __forceinline__ uint32_t sw_off(int r, int c) {   // bytes within one tile
    uint32_t off = (uint32_t)(r * ROW_BYTES + (c << 4));
    return off ^ ((off >> 3) & 0x70);
}

__global__ __launch_bounds__(256, 2)
void qkv_gemm_kernel(const float* __restrict__ bq,
                     const float* __restrict__ bk,
                     const float* __restrict__ bv)
{
    extern __shared__ __align__(1024) char smem[];
    const uint32_t sb = smem_u32(smem);

    const int tid  = threadIdx.x;
    const int warp = tid >> 5;
    const int lane = tid & 31;
    const int m0 = blockIdx.x * 128;
    const int n0 = blockIdx.y * 128;
    const int z  = blockIdx.z;

    const __half* Xh = g_xh;
    const __half* Wh = g_wh + (size_t)z * HDIM * HDIM;
    const float* bias = (z == 0) ? bq : (z == 1) ? bk : bv;
    __half* outp = (z == 0) ? g_qh : (z == 1) ? g_kh : g_vh;

    const int wm = (warp & 3) * 32;
    const int wn = (warp >> 2) * 64;

    float c[2][8][4];
    #pragma unroll
    for (int mt = 0; mt < 2; ++mt)
        #pragma unroll
        for (int nt = 0; nt < 8; ++nt)
            #pragma unroll
            for (int i = 0; i < 4; ++i) c[mt][nt][i] = 0.f;

    const int r0g = tid >> 3;          // 0..31 (+32 per pass)
    const int cg  = tid & 7;           // 16B chunk 0..7

    auto load_tile = [&](int kt, int buf) {
        const uint32_t sa  = sb + buf * STAGE_BYTES;
        const uint32_t sbm = sa + TILE_BYTES;
        const int k0 = kt * BK;
        #pragma unroll
        for (int i = 0; i < 4; ++i) {
            int r = r0g + i * 32;
            cp_async16(sa + sw_off(r, cg),
                       Xh + (size_t)(m0 + r) * HDIM + k0 + cg * 8);
            cp_async16(sbm + sw_off(r, cg),
                       Wh + (size_t)(n0 + r) * HDIM + k0 + cg * 8);
        }
        cp_commit();
    };

    load_tile(0, 0);
    load_tile(1, 1);

    const int a_row = wm + (lane & 15);                        // + mt*16
    const int a_ch0 = lane >> 4;                               // + kk/8
    const int b_row = wn + (lane & 7) + ((lane >> 4) << 3);    // + np*16
    const int b_ch0 = (lane >> 3) & 1;                         // + kk/8

    int buf = 0;
    for (int kt = 0; kt < NK; ++kt) {
        cp_wait<1>();
        __syncthreads();
        // buffer (kt+2)%3 == (kt-1)%3: all readers passed the barrier above
        if (kt + 2 < NK) {
            int nb = buf + 2; if (nb >= NSTAGE) nb -= NSTAGE;
            load_tile(kt + 2, nb);
        } else {
            cp_commit();               // keep group arithmetic exact
        }

        const uint32_t sa  = sb + buf * STAGE_BYTES;
        const uint32_t sbm = sa + TILE_BYTES;

        #pragma unroll
        for (int h = 0; h < 4; ++h) {          // kk = 16*h
            uint32_t a[2][4], b[4][4];
            #pragma unroll
            for (int mt = 0; mt < 2; ++mt)
                ldmatrix_x4(a[mt], sa + sw_off(a_row + mt * 16, 2 * h + a_ch0));
            #pragma unroll
            for (int np = 0; np < 4; ++np)
                ldmatrix_x4(b[np], sbm + sw_off(b_row + np * 16, 2 * h + b_ch0));
            #pragma unroll
            for (int mt = 0; mt < 2; ++mt)
                #pragma unroll
                for (int nt = 0; nt < 8; ++nt)
                    mma_f16(c[mt][nt], a[mt], &b[nt >> 1][(nt & 1) * 2]);
        }
        if (++buf == NSTAGE) buf = 0;
    }

    // ---- Epilogue: bias + fp16 into smem staging tile, then coalesced copy ----
    cp_wait<0>();
    __syncthreads();                       // pipeline smem now dead; reuse for staging
    {
        __half* tile = (__half*)smem;      // 128 rows x EPAD halfs = 34 KB
        const int g  = lane >> 2;
        const int tg = lane & 3;
        #pragma unroll
        for (int mt = 0; mt < 2; ++mt) {
            #pragma unroll
            for (int nt = 0; nt < 8; ++nt) {
                int row = wm + mt * 16 + g;            // local tile row
                int col = wn + nt * 8 + 2 * tg;
                float b0 = bias[n0 + col], b1 = bias[n0 + col + 1];
                *(__half2*)(tile + (size_t)row * EPAD + col) =
                    __floats2half2_rn(c[mt][nt][0] + b0, c[mt][nt][1] + b1);
                *(__half2*)(tile + (size_t)(row + 8) * EPAD + col) =
                    __floats2half2_rn(c[mt][nt][2] + b0, c[mt][nt][3] + b1);
            }
        }
        __syncthreads();
        // 128 rows x 256B; 2048 uint4 chunks; 8 per thread; fully coalesced stores
        #pragma unroll
        for (int it = 0; it < 8; ++it) {
            int idx = tid + it * 256;              // 0..2047
            int r = idx >> 4, ch = idx & 15;
            uint4 v = *(const uint4*)(tile + (size_t)r * EPAD + ch * 8);
            *(uint4*)(outp + (size_t)(m0 + r) * HDIM + n0 + ch * 8) = v;
        }
    }
}

// ---------------- sliding-window attention: K+V smem-tiled, 1 row/warp (R12 config) ----------------
#define A_ROWS 16
#define A_LOAD 24                      // A_ROWS + WIN halo
#define A_KBYTES (A_LOAD * 2048)       // 48 KB
#define A_SMEM (2 * A_KBYTES)          // 96 KB
#define A_THREADS 512

__device__ __forceinline__ void dot8(float& acc, uint4 a, uint4 b) {
    const __half2* ah = (const __half2*)&a;
    const __half2* bh = (const __half2*)&b;
    #pragma unroll
    for (int j = 0; j < 4; ++j) {
        float2 af = __half22float2(ah[j]);
        float2 bf = __half22float2(bh[j]);
        acc += af.x * bf.x + af.y * bf.y;
    }
}
__device__ __forceinline__ void axpy8(float o[8], float w, uint4 v) {
    const __half2* vh = (const __half2*)&v;
    #pragma unroll
    for (int j = 0; j < 4; ++j) {
        float2 f = __half22float2(vh[j]);
        o[2 * j]     += w * f.x;
        o[2 * j + 1] += w * f.y;
    }
}

__global__ __launch_bounds__(A_THREADS, 2) void attn_kernel(float* __restrict__ out)
{
    extern __shared__ __align__(16) char asmem[];
    const __half* ks = (const __half*)asmem;
    const __half* vs = (const __half*)(asmem + A_KBYTES);
    const uint32_t sb = smem_u32(asmem);

    const int tid = threadIdx.x;
    const int r0  = blockIdx.x * A_ROWS;

    #pragma unroll
    for (int p = 0; p < 6; ++p) {
        int gidx = tid + p * A_THREADS;        // 0..3071
        int s = gidx >> 7, cidx = gidx & 127;
        int gr = r0 - WIN + s; if (gr < 0) gr = 0;
        cp_async16(sb + s * 2048 + cidx * 16,
                   g_kh + (size_t)gr * HDIM + cidx * 8);
        cp_async16(sb + A_KBYTES + s * 2048 + cidx * 16,
                   g_vh + (size_t)gr * HDIM + cidx * 8);
    }
    cp_commit();
    cp_wait<0>();
    __syncthreads();

    const int warp = tid >> 5;
    const int lane = tid & 31;

    const int lr  = warp;                  // 0..15
    const int row = r0 + lr;
    const int t   = row & (TLEN - 1);
    const int wstart = (t < WIN) ? (WIN - t) : 0;

    const uint4* q4 = (const uint4*)(g_qh + (size_t)row * HDIM);

    float acc[WSZ];
    #pragma unroll
    for (int w = 0; w < WSZ; ++w) acc[w] = 0.f;

    if (wstart == 0) {
        #pragma unroll
        for (int i = 0; i < 4; ++i) {
            const int idx = lane + i * 32;
            const uint4 qv = q4[idx];
            #pragma unroll
            for (int w = 0; w < WSZ; ++w) {
                const uint4 kv = *(const uint4*)(ks + (size_t)(lr + w) * HDIM + idx * 8);
                dot8(acc[w], qv, kv);
            }
        }
    } else {
        #pragma unroll
        for (int i = 0; i < 4; ++i) {
            const int idx = lane + i * 32;
            const uint4 qv = q4[idx];
            #pragma unroll
            for (int w = 0; w < WSZ; ++w) {
                if (w >= wstart) {
                    const uint4 kv = *(const uint4*)(ks + (size_t)(lr + w) * HDIM + idx * 8);
                    dot8(acc[w], qv, kv);
                }
            }
        }
    }

    float wgt[WSZ];
    float mx = -1e30f;
    #pragma unroll
    for (int w = 0; w < WSZ; ++w) {
        float v = acc[w];
        #pragma unroll
        for (int off = 16; off; off >>= 1)
            v += __shfl_xor_sync(0xFFFFFFFFu, v, off);
        float s = (w >= wstart) ? v * 0.03125f : -1e30f;   // 1/sqrt(1024)
        wgt[w] = s;
        mx = fmaxf(mx, s);
    }
    float den = 0.f;
    #pragma unroll
    for (int w = 0; w < WSZ; ++w) {
        float e = (w >= wstart) ? __expf(wgt[w] - mx) : 0.f;
        wgt[w] = e;
        den += e;
    }
    const float inv = 1.f / den;
    #pragma unroll
    for (int w = 0; w < WSZ; ++w) wgt[w] *= inv;

    #pragma unroll
    for (int i = 0; i < 4; ++i) {
        const int idx = lane + i * 32;
        float o[8];
        #pragma unroll
        for (int x = 0; x < 8; ++x) o[x] = 0.f;
        if (wstart == 0) {
            #pragma unroll
            for (int w = 0; w < WSZ; ++w) {
                const uint4 vv = *(const uint4*)(vs + (size_t)(lr + w) * HDIM + idx * 8);
                axpy8(o, wgt[w], vv);
            }
        } else {
            #pragma unroll
            for (int w = 0; w < WSZ; ++w) {
                if (w >= wstart) {
                    const uint4 vv = *(const uint4*)(vs + (size_t)(lr + w) * HDIM + idx * 8);
                    axpy8(o, wgt[w], vv);
                }
            }
        }
        float4* op = (float4*)(out + (size_t)row * HDIM + idx * 8);
        op[0] = make_float4(o[0], o[1], o[2], o[3]);
        op[1] = make_float4(o[4], o[5], o[6], o[7]);
    }
}

// ---------------- launch ----------------
extern "C" void kernel_launch(void* const* d_in, const int* in_sizes, int n_in,
                              void* d_out, int out_size)
{
    const float* states = (const float*)d_in[0];
    const float* Wq = (const float*)d_in[1];
    const float* bq = (const float*)d_in[2];
    const float* Wk = (const float*)d_in[3];
    const float* bk = (const float*)d_in[4];
    const float* Wv = (const float*)d_in[5];
    const float* bv = (const float*)d_in[6];
    float* out = (float*)d_out;

    cudaFuncSetAttribute(qkv_gemm_kernel,
                         cudaFuncAttributeMaxDynamicSharedMemorySize, G_SMEM);
    cudaFuncSetAttribute(attn_kernel,
                         cudaFuncAttributeMaxDynamicSharedMemorySize, A_SMEM);

    conv_kernel<<<9728, 256>>>(states, Wq, Wk, Wv);

    dim3 grid(MROWS / 128, HDIM / 128, 3);   // 128 x 8 x 3
    qkv_gemm_kernel<<<grid, 256, G_SMEM>>>(bq, bk, bv);

    attn_kernel<<<MROWS / A_ROWS, A_THREADS, A_SMEM>>>(out);
}